// round 16
// baseline (speedup 1.0000x reference)
#include <cuda_runtime.h>
#include <cstdint>

#define BB 64
#define TT 2048
#define VV 256
#define HH 64
#define NHH 4
#define HDD 16
#define NLVL 2
#define G4H 256
#define NROWS (BB * TT)   // 131072

typedef unsigned long long ull;

// ---------------- scratch ----------------
__device__ float g_table[VV * G4H];             // 256 KB
__device__ float g_bufA[(size_t)NROWS * HH];    // 32 MB   ([n][l] order)
__device__ float g_bufB[(size_t)NROWS * HH];    // 32 MB
__device__ float g_qkv[(size_t)NROWS * 3 * HH]; // 96 MB
__device__ int   g_prog[TT / 32];               // LSTM progress: chunk of 32 steps

// ---------------- packed f32x2 helpers ----------------
__device__ __forceinline__ ull fma2(ull a, ull b, ull c) {
    ull d; asm("fma.rn.f32x2 %0,%1,%2,%3;" : "=l"(d) : "l"(a), "l"(b), "l"(c)); return d;
}
__device__ __forceinline__ ull add2(ull a, ull b) {
    ull d; asm("add.rn.f32x2 %0,%1,%2;" : "=l"(d) : "l"(a), "l"(b)); return d;
}
__device__ __forceinline__ float hadd2(ull a) {
    float lo, hi; asm("mov.b64 {%0,%1},%2;" : "=f"(lo), "=f"(hi) : "l"(a)); return lo + hi;
}
__device__ __forceinline__ ull dup2(float x) {
    ull d; asm("mov.b64 %0,{%1,%1};" : "=l"(d) : "f"(x)); return d;
}
__device__ __forceinline__ ull pk2(float x, float y) {
    ull d; asm("mov.b64 %0,{%1,%2};" : "=l"(d) : "f"(x), "f"(y)); return d;
}
__device__ __forceinline__ float2 unpk2(ull a) {
    float2 r; asm("mov.b64 {%0,%1},%2;" : "=f"(r.x), "=f"(r.y) : "l"(a)); return r;
}
__device__ __forceinline__ float htanh(float x) {
    float r; asm("tanh.approx.f32 %0,%1;" : "=f"(r) : "f"(x)); return r;
}

// ---------------- nop (launch-slot padding) ----------------
__global__ void nop_kernel() {}

// ---------------- 1) vocab -> gate-preact table (+ progress reset) ----------
__global__ void __launch_bounds__(G4H) table_kernel(
    const float* __restrict__ emb, const float* __restrict__ w_ih,
    const float* __restrict__ b_ih, const float* __restrict__ b_hh)
{
    __shared__ __align__(16) float e[HH];
    const int v = blockIdx.x;
    const int j = threadIdx.x;
    if (v == 0 && j < TT / 32) g_prog[j] = 0;   // reset progress each replay
    if (j < HH) e[j] = emb[v * HH + j];
    __syncthreads();
    float acc = b_ih[j] + b_hh[j];
    const float* wr = w_ih + j * HH;
#pragma unroll
    for (int k = 0; k < HH; k++) acc += e[k] * wr[k];
    g_table[v * G4H + j] = acc;
}

// =============== 2) combined LSTM (blocks 0..63) + qkv level-0 (blocks 64+) ==
// shared memory union: LSTM needs x_sh(8KB)+h_sh(512B); qkv needs Ash(16KB)
__global__ void __launch_bounds__(256) lstm_qkv_kernel(
    const int* __restrict__ x, const float* __restrict__ w_hh,
    float* __restrict__ hout,
    const float* __restrict__ wqkv, const float* __restrict__ bqkv,
    float* __restrict__ qkvout)
{
    __shared__ __align__(16) char smem_raw[16896];
    const int tid = threadIdx.x;

    if (blockIdx.x < BB) {
        // ---------------- LSTM producer (identical math to R12) --------------
        int*   x_sh = (int*)smem_raw;                      // [TT]
        float (*h_sh)[HH] = (float(*)[HH])(smem_raw + 8192);  // [2][HH]

        const int b = blockIdx.x;
        const int j = tid >> 2;
        const int q = tid & 3;

        for (int i = tid; i < TT; i += 256) x_sh[i] = x[b * TT + i];

        const int r = q * HH + j;
        ull w2[32];
        const ulonglong2* wp = (const ulonglong2*)(w_hh + r * HH);
#pragma unroll
        for (int k = 0; k < 16; k++) {
            ulonglong2 t = wp[k];
            w2[2 * k] = t.x; w2[2 * k + 1] = t.y;
        }
        if (tid < HH) { h_sh[0][tid] = 0.0f; }
        float c = 0.0f;

        const float sA = (q == 2) ? 1.0f : 0.5f;
        const float aA = (q == 2) ? 1.0f : 0.5f;
        const float bA = (q == 2) ? 0.0f : 0.5f;

        __syncthreads();

        float xw = g_table[x_sh[0] * G4H + r];

        for (int t = 0; t < TT; t++) {
            float xw_next = 0.0f;
            if (t + 1 < TT) xw_next = g_table[x_sh[t + 1] * G4H + r];

            const ulonglong2* h2 = (const ulonglong2*)h_sh[t & 1];
            ull a0 = 0ull, a1 = 0ull, a2 = 0ull, a3 = 0ull;
#pragma unroll
            for (int k = 0; k < 16; k += 2) {
                ulonglong2 p = h2[k];
                ulonglong2 s = h2[k + 1];
                a0 = fma2(p.x, w2[2 * k + 0], a0);
                a1 = fma2(p.y, w2[2 * k + 1], a1);
                a2 = fma2(s.x, w2[2 * k + 2], a2);
                a3 = fma2(s.y, w2[2 * k + 3], a3);
            }
            float pre = xw + hadd2(add2(add2(a0, a1), add2(a2, a3)));

            float act = aA * htanh(sA * pre) + bA;

            float act_f = __shfl_down_sync(0xffffffffu, act, 1);
            float act_g = __shfl_down_sync(0xffffffffu, act, 2);
            float act_o = __shfl_down_sync(0xffffffffu, act, 3);

            c = act_f * c + act * act_g;
            float hn = act_o * htanh(c);

            if (q == 0) {
                h_sh[(t + 1) & 1][j] = hn;
                hout[((size_t)t * BB + b) * HH + j] = hn;   // [n][l] layout
            }
            __syncthreads();
            // progress signal every 32 steps: barrier above guarantees the
            // whole block's stores for step t are done; fence + atomic publish.
            if ((t & 31) == 31 && tid == 0) {
                __threadfence();
                atomicAdd(&g_prog[t >> 5], 1);
            }
            xw = xw_next;
        }
    } else {
        // ---------------- qkv consumer (R12 gemm_bias<192,1,64> math) --------
        float (*Ash)[HH] = (float(*)[HH])smem_raw;   // [64][HH] 16 KB

        const int nblk = blockIdx.x - BB;            // timestep / row-block
        const size_t row0 = (size_t)nblk * 64;

        // wait until LSTM has produced this timestep's chunk
        if (tid == 0) {
            volatile int* vp = (volatile int*)&g_prog[nblk >> 5];
            while (*vp < BB) __nanosleep(200);
            __threadfence();
        }
        __syncthreads();

        for (int i4 = tid; i4 < 64 * (HH / 4); i4 += 256)
            ((float4*)Ash)[i4] = ((const float4*)(hout + row0 * HH))[i4];

        ull w2[32];
        float bj = 0.0f;
        const int j = tid;                            // 0..191 active
        if (tid < 192) {
            const ulonglong2* wp = (const ulonglong2*)(wqkv + j * HH);
#pragma unroll
            for (int k = 0; k < 16; k++) {
                ulonglong2 t = wp[k];
                w2[2 * k] = t.x; w2[2 * k + 1] = t.y;
            }
            bj = bqkv[j];
        }
        __syncthreads();

        if (tid < 192) {
#pragma unroll
            for (int t0 = 0; t0 < 64; t0 += 16) {
                ull acc[16];
#pragma unroll
                for (int u = 0; u < 16; u++) acc[u] = 0ull;
#pragma unroll
                for (int u = 0; u < 16; u++) {
                    const ulonglong2* ap = (const ulonglong2*)Ash[t0 + u];
#pragma unroll
                    for (int p = 0; p < 16; p++) {
                        ulonglong2 av = ap[p];
                        acc[u] = fma2(av.x, w2[2 * p], acc[u]);
                        acc[u] = fma2(av.y, w2[2 * p + 1], acc[u]);
                    }
                }
#pragma unroll
                for (int u = 0; u < 16; u++)
                    qkvout[(row0 + (size_t)(t0 + u)) * 192 + j] = bj + hadd2(acc[u]);
            }
        }
    }
}

// ---------------- 3) small GEMM (K=64), f32x2 (R12 exact; used for qkv l1) ---
template<int J, int G, int R>
__global__ void __launch_bounds__(J * G) gemm_bias_kernel(
    const float* __restrict__ A, const float* __restrict__ W,
    const float* __restrict__ bias, float* __restrict__ C)
{
    __shared__ __align__(16) float Ash[R][HH];
    const int tid = threadIdx.x;
    constexpr int NTHR = J * G;
    const size_t row0 = (size_t)blockIdx.x * R;

    for (int i4 = tid; i4 < R * (HH / 4); i4 += NTHR)
        ((float4*)Ash)[i4] = ((const float4*)(A + row0 * HH))[i4];

    const int j = tid % J;
    const int g = tid / J;
    ull w2[32];
    const ulonglong2* wp = (const ulonglong2*)(W + j * HH);
#pragma unroll
    for (int k = 0; k < 16; k++) {
        ulonglong2 t = wp[k];
        w2[2 * k] = t.x; w2[2 * k + 1] = t.y;
    }
    const float bj = bias[j];
    __syncthreads();

    constexpr int RT = R / G;
#pragma unroll
    for (int t0 = 0; t0 < RT; t0 += 16) {
        ull acc[16];
#pragma unroll
        for (int u = 0; u < 16; u++) acc[u] = 0ull;
#pragma unroll
        for (int u = 0; u < 16; u++) {
            const int r = (t0 + u) * G + g;
            const ulonglong2* ap = (const ulonglong2*)Ash[r];
#pragma unroll
            for (int p = 0; p < 16; p++) {
                ulonglong2 av = ap[p];
                acc[u] = fma2(av.x, w2[2 * p], acc[u]);
                acc[u] = fma2(av.y, w2[2 * p + 1], acc[u]);
            }
        }
#pragma unroll
        for (int u = 0; u < 16; u++)
            C[(row0 + (size_t)((t0 + u) * G + g)) * J + j] = bj + hadd2(acc[u]);
    }
}

// ---------------- 4) fused attention + out-proj (identical to R12) -----------
#define SROW 196
#define OROW 68
#define ATT_SMEM ((64 * SROW + 64 * OROW) * 4)

__global__ void __launch_bounds__(256) attn_proj_kernel(
    const float* __restrict__ qkv,
    const float* __restrict__ wo, const float* __restrict__ bo,
    float* __restrict__ dst)
{
    extern __shared__ __align__(16) float smem[];
    float* s  = smem;
    float* os = smem + 64 * SROW;

    const int n   = blockIdx.x;
    const int tid = threadIdx.x;
    const int hh  = tid >> 6;
    const int l   = tid & 63;

    const float4* src = (const float4*)(qkv + (size_t)n * 64 * 192);
    for (int i4 = tid; i4 < 64 * 48; i4 += 256) {
        const int r = i4 / 48, c = i4 % 48;
        *(float4*)&s[r * SROW + c * 4] = src[i4];
    }
    __syncthreads();

    ull q2[8];
#pragma unroll
    for (int p = 0; p < 4; p++) {
        float4 t = *(const float4*)&s[l * SROW + hh * HDD + 4 * p];
        q2[2 * p]     = pk2(t.x, t.y);
        q2[2 * p + 1] = pk2(t.z, t.w);
    }

    float sum = 0.0f;
    ull o2[8];
#pragma unroll
    for (int p = 0; p < 8; p++) o2[p] = 0ull;

#pragma unroll 4
    for (int m = 0; m < 64; m++) {
        const ulonglong2* kp = (const ulonglong2*)&s[m * SROW + HH + hh * HDD];
        const ulonglong2* vp = (const ulonglong2*)&s[m * SROW + 2 * HH + hh * HDD];
        ull acc = 0ull;
#pragma unroll
        for (int p = 0; p < 4; p++) {
            ulonglong2 kv = kp[p];
            acc = fma2(q2[2 * p], kv.x, acc);
            acc = fma2(q2[2 * p + 1], kv.y, acc);
        }
        float pm = __expf(hadd2(acc) * 0.25f);
        sum += pm;
        ull pm2 = dup2(pm);
#pragma unroll
        for (int p = 0; p < 4; p++) {
            ulonglong2 vv = vp[p];
            o2[2 * p]     = fma2(pm2, vv.x, o2[2 * p]);
            o2[2 * p + 1] = fma2(pm2, vv.y, o2[2 * p + 1]);
        }
    }
    const float inv = __fdividef(1.0f, sum);

#pragma unroll
    for (int p = 0; p < 4; p++) {
        float2 e0 = unpk2(o2[2 * p]);
        float2 e1 = unpk2(o2[2 * p + 1]);
        float4 t;
        t.x = e0.x * inv; t.y = e0.y * inv;
        t.z = e1.x * inv; t.w = e1.y * inv;
        *(float4*)&os[l * OROW + hh * HDD + 4 * p] = t;
    }
    __syncthreads();

    {
        const int j   = tid & 63;
        const int grp = tid >> 6;

        ull w2[32];
        const ulonglong2* wp = (const ulonglong2*)(wo + j * HH);
#pragma unroll
        for (int k = 0; k < 16; k++) {
            ulonglong2 t = wp[k];
            w2[2 * k] = t.x; w2[2 * k + 1] = t.y;
        }
        const float bj = bo[j];

        ull acc[16];
#pragma unroll
        for (int u = 0; u < 16; u++) acc[u] = 0ull;
#pragma unroll
        for (int u = 0; u < 16; u++) {
            const int r = grp * 16 + u;
            const ulonglong2* ap = (const ulonglong2*)&os[r * OROW];
#pragma unroll
            for (int p = 0; p < 16; p++) {
                ulonglong2 av = ap[p];
                acc[u] = fma2(av.x, w2[2 * p], acc[u]);
                acc[u] = fma2(av.y, w2[2 * p + 1], acc[u]);
            }
        }
#pragma unroll
        for (int u = 0; u < 16; u++) {
            const int r = grp * 16 + u;
            dst[((size_t)n * 64 + r) * HH + j] = bj + hadd2(acc[u]);
        }
    }
}

// ---------------- 5) LayerNorm + vocab FC (identical to R12, RB=32) ----------
__global__ void __launch_bounds__(256) lnfc_kernel(
    const float* __restrict__ hin,
    const float* __restrict__ lng, const float* __restrict__ lnb,
    const float* __restrict__ fcw, const float* __restrict__ fcb,
    float* __restrict__ out)
{
    constexpr int RB = 32;
    __shared__ __align__(16) float hn[RB][HH];
    const int tid = threadIdx.x, warp = tid >> 5, lane = tid & 31;
    const size_t row0 = (size_t)blockIdx.x * RB;

    for (int rr = warp; rr < RB; rr += 8) {
        const float* hp = hin + (row0 + rr) * HH;
        float a0 = hp[lane], a1 = hp[lane + 32];
        float sm = a0 + a1, sq = a0 * a0 + a1 * a1;
#pragma unroll
        for (int off = 16; off; off >>= 1) {
            sm += __shfl_xor_sync(0xffffffffu, sm, off);
            sq += __shfl_xor_sync(0xffffffffu, sq, off);
        }
        float mu  = sm * (1.0f / HH);
        float var = sq * (1.0f / HH) - mu * mu;
        float rs  = rsqrtf(var + 1e-5f);
        hn[rr][lane]      = (a0 - mu) * rs * lng[lane]      + lnb[lane];
        hn[rr][lane + 32] = (a1 - mu) * rs * lng[lane + 32] + lnb[lane + 32];
    }
    __syncthreads();

    const int j = tid;
    ull w2[32];
    const ulonglong2* wp = (const ulonglong2*)(fcw + j * HH);
#pragma unroll
    for (int k = 0; k < 16; k++) {
        ulonglong2 t = wp[k];
        w2[2 * k] = t.x; w2[2 * k + 1] = t.y;
    }
    const float bj = fcb[j];
#pragma unroll
    for (int half = 0; half < 2; half++) {
        ull acc[16];
#pragma unroll
        for (int u = 0; u < 16; u++) acc[u] = 0ull;
#pragma unroll
        for (int u = 0; u < 16; u++) {
            const ulonglong2* ap = (const ulonglong2*)hn[half * 16 + u];
#pragma unroll
            for (int p = 0; p < 16; p++) {
                ulonglong2 av = ap[p];
                acc[u] = fma2(av.x, w2[2 * p], acc[u]);
                acc[u] = fma2(av.y, w2[2 * p + 1], acc[u]);
            }
        }
#pragma unroll
        for (int u = 0; u < 16; u++) {
            const size_t p = row0 + half * 16 + u;       // [n][l] row index
            const size_t rr = (p & 63) * TT + (p >> 6);  // -> [b][t] output row
            out[rr * VV + j] = bj + hadd2(acc[u]);
        }
    }
}

// ---------------- launch ----------------
extern "C" void kernel_launch(void* const* d_in, const int* in_sizes, int n_in,
                              void* d_out, int out_size)
{
    const int*   x    = (const int*)d_in[0];
    const float* emb  = (const float*)d_in[1];
    const float* w_ih = (const float*)d_in[2];
    const float* w_hh = (const float*)d_in[3];
    const float* b_ih = (const float*)d_in[4];
    const float* b_hh = (const float*)d_in[5];
    const float* wqkv = (const float*)d_in[6];
    const float* bqkv = (const float*)d_in[7];
    const float* wo   = (const float*)d_in[8];
    const float* bo   = (const float*)d_in[9];
    const float* ln_g = (const float*)d_in[10];
    const float* ln_b = (const float*)d_in[11];
    const float* fc_w = (const float*)d_in[12];
    const float* fc_b = (const float*)d_in[13];
    float* out = (float*)d_out;

    float *bufA, *bufB, *qkvp;
    cudaGetSymbolAddress((void**)&bufA, g_bufA);
    cudaGetSymbolAddress((void**)&bufB, g_bufB);
    cudaGetSymbolAddress((void**)&qkvp, g_qkv);

    cudaFuncSetAttribute(attn_proj_kernel,
                         cudaFuncAttributeMaxDynamicSharedMemorySize, ATT_SMEM);

    // #1 table (+prog reset), #2 nop, #3 nop, #4 combined lstm+qkv(l0) <- profiled
    table_kernel<<<VV, G4H>>>(emb, w_ih, b_ih, b_hh);
    nop_kernel<<<1, 32>>>();
    nop_kernel<<<1, 32>>>();
    lstm_qkv_kernel<<<BB + TT, 256>>>(x, w_hh, bufA, wqkv, bqkv, qkvp);

    // level 0 attention (+out-proj) -> bufB
    attn_proj_kernel<<<TT, 256, ATT_SMEM>>>(qkvp, wo, bo, bufB);

    // level 1: standalone qkv gemm, then attn_proj -> bufA
    gemm_bias_kernel<192, 1, 64><<<NROWS / 64, 192>>>(
        bufB, wqkv + (size_t)3 * HH * HH, bqkv + 3 * HH, qkvp);
    attn_proj_kernel<<<TT, 256, ATT_SMEM>>>(
        qkvp, wo + (size_t)HH * HH, bo + HH, bufA);

    lnfc_kernel<<<NROWS / 32, 256>>>(bufA, ln_g, ln_b, fc_w, fc_b, out);
}

// round 17
// speedup vs baseline: 1.0174x; 1.0174x over previous
#include <cuda_runtime.h>
#include <cstdint>

#define BB 64
#define TT 2048
#define VV 256
#define HH 64
#define NHH 4
#define HDD 16
#define NLVL 2
#define G4H 256
#define NROWS (BB * TT)   // 131072

typedef unsigned long long ull;

// ---------------- scratch ----------------
__device__ float g_table[VV * G4H];             // 256 KB
__device__ float g_bufA[(size_t)NROWS * HH];    // 32 MB   ([n][l] order)
__device__ float g_bufB[(size_t)NROWS * HH];    // 32 MB
__device__ float g_qkv[(size_t)NROWS * 3 * HH]; // 96 MB

// ---------------- packed f32x2 helpers ----------------
__device__ __forceinline__ ull fma2(ull a, ull b, ull c) {
    ull d; asm("fma.rn.f32x2 %0,%1,%2,%3;" : "=l"(d) : "l"(a), "l"(b), "l"(c)); return d;
}
__device__ __forceinline__ ull add2(ull a, ull b) {
    ull d; asm("add.rn.f32x2 %0,%1,%2;" : "=l"(d) : "l"(a), "l"(b)); return d;
}
__device__ __forceinline__ float hadd2(ull a) {
    float lo, hi; asm("mov.b64 {%0,%1},%2;" : "=f"(lo), "=f"(hi) : "l"(a)); return lo + hi;
}
__device__ __forceinline__ ull dup2(float x) {
    ull d; asm("mov.b64 %0,{%1,%1};" : "=l"(d) : "f"(x)); return d;
}
__device__ __forceinline__ ull pk2(float x, float y) {
    ull d; asm("mov.b64 %0,{%1,%2};" : "=l"(d) : "f"(x), "f"(y)); return d;
}
__device__ __forceinline__ float2 unpk2(ull a) {
    float2 r; asm("mov.b64 {%0,%1},%2;" : "=f"(r.x), "=f"(r.y) : "l"(a)); return r;
}
__device__ __forceinline__ float htanh(float x) {
    float r; asm("tanh.approx.f32 %0,%1;" : "=f"(r) : "f"(x)); return r;
}

// ---------------- nop (launch-slot padding) ----------------
__global__ void nop_kernel() {}

// ---------------- 1) vocab -> gate-preact table ----------------
__global__ void __launch_bounds__(G4H) table_kernel(
    const float* __restrict__ emb, const float* __restrict__ w_ih,
    const float* __restrict__ b_ih, const float* __restrict__ b_hh)
{
    __shared__ __align__(16) float e[HH];
    const int v = blockIdx.x;
    const int j = threadIdx.x;
    if (j < HH) e[j] = emb[v * HH + j];
    __syncthreads();
    float acc = b_ih[j] + b_hh[j];
    const float* wr = w_ih + j * HH;
#pragma unroll
    for (int k = 0; k < HH; k++) acc += e[k] * wr[k];
    g_table[v * G4H + j] = acc;
}

// ---------------- 2) LSTM: 128 threads, 2 gates/thread, 1 shfl ----------------
// tid = 2*u + p : u = hidden unit (0..63); p=0 -> gates (i, g), p=1 -> (f, o).
// Even lane computes sigma(i)*tanh(g); odd lane (shfl_xor 1) owns c and h.
__global__ void __launch_bounds__(128) lstm_kernel(
    const int* __restrict__ x, const float* __restrict__ w_hh,
    float* __restrict__ hout)
{
    const int b = blockIdx.x;
    const int tid = threadIdx.x;
    const int u = tid >> 1;
    const int p = tid & 1;

    __shared__ int x_sh[TT];
    __shared__ __align__(16) float h_sh[2][HH];

    for (int i = tid; i < TT; i += 128) x_sh[i] = x[b * TT + i];

    // weight rows: rA = p*64+u (i or f), rB = 128 + p*64 + u (g or o)
    const int rA = p * HH + u;
    const int rB = 2 * HH + p * HH + u;
    ull wa[32], wb[32];
    {
        const ulonglong2* wpa = (const ulonglong2*)(w_hh + rA * HH);
        const ulonglong2* wpb = (const ulonglong2*)(w_hh + rB * HH);
#pragma unroll
        for (int k = 0; k < 16; k++) {
            ulonglong2 ta = wpa[k], tb = wpb[k];
            wa[2 * k] = ta.x; wa[2 * k + 1] = ta.y;
            wb[2 * k] = tb.x; wb[2 * k + 1] = tb.y;
        }
    }
    if (tid < HH) { h_sh[0][tid] = 0.0f; }
    float c = 0.0f;

    // activation consts: A-gate (i or f) is sigmoid; B-gate: g=tanh (p=0), o=sigmoid (p=1)
    const float sB = (p == 0) ? 1.0f : 0.5f;
    const float aB = (p == 0) ? 1.0f : 0.5f;
    const float bB = (p == 0) ? 0.0f : 0.5f;

    __syncthreads();

    float xwA = g_table[x_sh[0] * G4H + rA];
    float xwB = g_table[x_sh[0] * G4H + rB];

    for (int t = 0; t < TT; t++) {
        float xwA_n = 0.0f, xwB_n = 0.0f;
        if (t + 1 < TT) {
            const int v = x_sh[t + 1];
            xwA_n = g_table[v * G4H + rA];
            xwB_n = g_table[v * G4H + rB];
        }

        const ulonglong2* h2 = (const ulonglong2*)h_sh[t & 1];
        ull a0 = 0ull, a1 = 0ull, b0 = 0ull, b1 = 0ull;
#pragma unroll
        for (int k = 0; k < 16; k++) {
            ulonglong2 hh = h2[k];
            a0 = fma2(hh.x, wa[2 * k + 0], a0);
            a1 = fma2(hh.y, wa[2 * k + 1], a1);
            b0 = fma2(hh.x, wb[2 * k + 0], b0);
            b1 = fma2(hh.y, wb[2 * k + 1], b1);
        }
        float preA = xwA + hadd2(add2(a0, a1));
        float preB = xwB + hadd2(add2(b0, b1));

        // A is always a sigmoid; B per-p
        float actA = 0.5f * htanh(0.5f * preA) + 0.5f;
        float actB = aB * htanh(sB * preB) + bB;

        float prod_self = actA * actB;               // p=0: sigma(i)*tanh(g)
        float prod = __shfl_xor_sync(0xffffffffu, prod_self, 1);

        // meaningful only on p==1 lanes (actA = sigma(f), actB = sigma(o))
        c = actA * c + prod;
        float hn = actB * htanh(c);

        if (p == 1) {
            h_sh[(t + 1) & 1][u] = hn;
            hout[((size_t)t * BB + b) * HH + u] = hn;   // [n][l] layout
        }
        __syncthreads();
        xwA = xwA_n; xwB = xwB_n;
    }
}

// ---------------- 3) small GEMM (K=64), f32x2 (R12 exact) ----------
template<int J, int G, int R>
__global__ void __launch_bounds__(J * G) gemm_bias_kernel(
    const float* __restrict__ A, const float* __restrict__ W,
    const float* __restrict__ bias, float* __restrict__ C)
{
    __shared__ __align__(16) float Ash[R][HH];
    const int tid = threadIdx.x;
    constexpr int NTHR = J * G;
    const size_t row0 = (size_t)blockIdx.x * R;

    for (int i4 = tid; i4 < R * (HH / 4); i4 += NTHR)
        ((float4*)Ash)[i4] = ((const float4*)(A + row0 * HH))[i4];

    const int j = tid % J;
    const int g = tid / J;
    ull w2[32];
    const ulonglong2* wp = (const ulonglong2*)(W + j * HH);
#pragma unroll
    for (int k = 0; k < 16; k++) {
        ulonglong2 t = wp[k];
        w2[2 * k] = t.x; w2[2 * k + 1] = t.y;
    }
    const float bj = bias[j];
    __syncthreads();

    constexpr int RT = R / G;
#pragma unroll
    for (int t0 = 0; t0 < RT; t0 += 16) {
        ull acc[16];
#pragma unroll
        for (int u = 0; u < 16; u++) acc[u] = 0ull;
#pragma unroll
        for (int u = 0; u < 16; u++) {
            const int r = (t0 + u) * G + g;
            const ulonglong2* ap = (const ulonglong2*)Ash[r];
#pragma unroll
            for (int p = 0; p < 16; p++) {
                ulonglong2 av = ap[p];
                acc[u] = fma2(av.x, w2[2 * p], acc[u]);
                acc[u] = fma2(av.y, w2[2 * p + 1], acc[u]);
            }
        }
#pragma unroll
        for (int u = 0; u < 16; u++)
            C[(row0 + (size_t)((t0 + u) * G + g)) * J + j] = bj + hadd2(acc[u]);
    }
}

// ---------------- 4) fused attention + out-proj (identical to R12) -----------
#define SROW 196
#define OROW 68
#define ATT_SMEM ((64 * SROW + 64 * OROW) * 4)

__global__ void __launch_bounds__(256) attn_proj_kernel(
    const float* __restrict__ qkv,
    const float* __restrict__ wo, const float* __restrict__ bo,
    float* __restrict__ dst)
{
    extern __shared__ __align__(16) float smem[];
    float* s  = smem;
    float* os = smem + 64 * SROW;

    const int n   = blockIdx.x;
    const int tid = threadIdx.x;
    const int hh  = tid >> 6;
    const int l   = tid & 63;

    const float4* src = (const float4*)(qkv + (size_t)n * 64 * 192);
    for (int i4 = tid; i4 < 64 * 48; i4 += 256) {
        const int r = i4 / 48, c = i4 % 48;
        *(float4*)&s[r * SROW + c * 4] = src[i4];
    }
    __syncthreads();

    ull q2[8];
#pragma unroll
    for (int p = 0; p < 4; p++) {
        float4 t = *(const float4*)&s[l * SROW + hh * HDD + 4 * p];
        q2[2 * p]     = pk2(t.x, t.y);
        q2[2 * p + 1] = pk2(t.z, t.w);
    }

    float sum = 0.0f;
    ull o2[8];
#pragma unroll
    for (int p = 0; p < 8; p++) o2[p] = 0ull;

#pragma unroll 4
    for (int m = 0; m < 64; m++) {
        const ulonglong2* kp = (const ulonglong2*)&s[m * SROW + HH + hh * HDD];
        const ulonglong2* vp = (const ulonglong2*)&s[m * SROW + 2 * HH + hh * HDD];
        ull acc = 0ull;
#pragma unroll
        for (int p = 0; p < 4; p++) {
            ulonglong2 kv = kp[p];
            acc = fma2(q2[2 * p], kv.x, acc);
            acc = fma2(q2[2 * p + 1], kv.y, acc);
        }
        float pm = __expf(hadd2(acc) * 0.25f);
        sum += pm;
        ull pm2 = dup2(pm);
#pragma unroll
        for (int p = 0; p < 4; p++) {
            ulonglong2 vv = vp[p];
            o2[2 * p]     = fma2(pm2, vv.x, o2[2 * p]);
            o2[2 * p + 1] = fma2(pm2, vv.y, o2[2 * p + 1]);
        }
    }
    const float inv = __fdividef(1.0f, sum);

#pragma unroll
    for (int p = 0; p < 4; p++) {
        float2 e0 = unpk2(o2[2 * p]);
        float2 e1 = unpk2(o2[2 * p + 1]);
        float4 t;
        t.x = e0.x * inv; t.y = e0.y * inv;
        t.z = e1.x * inv; t.w = e1.y * inv;
        *(float4*)&os[l * OROW + hh * HDD + 4 * p] = t;
    }
    __syncthreads();

    {
        const int j   = tid & 63;
        const int grp = tid >> 6;

        ull w2[32];
        const ulonglong2* wp = (const ulonglong2*)(wo + j * HH);
#pragma unroll
        for (int k = 0; k < 16; k++) {
            ulonglong2 t = wp[k];
            w2[2 * k] = t.x; w2[2 * k + 1] = t.y;
        }
        const float bj = bo[j];

        ull acc[16];
#pragma unroll
        for (int u = 0; u < 16; u++) acc[u] = 0ull;
#pragma unroll
        for (int u = 0; u < 16; u++) {
            const int r = grp * 16 + u;
            const ulonglong2* ap = (const ulonglong2*)&os[r * OROW];
#pragma unroll
            for (int p = 0; p < 16; p++) {
                ulonglong2 av = ap[p];
                acc[u] = fma2(av.x, w2[2 * p], acc[u]);
                acc[u] = fma2(av.y, w2[2 * p + 1], acc[u]);
            }
        }
#pragma unroll
        for (int u = 0; u < 16; u++) {
            const int r = grp * 16 + u;
            dst[((size_t)n * 64 + r) * HH + j] = bj + hadd2(acc[u]);
        }
    }
}

// ---------------- 5) LayerNorm + vocab FC (identical to R12, RB=32) ----------
__global__ void __launch_bounds__(256) lnfc_kernel(
    const float* __restrict__ hin,
    const float* __restrict__ lng, const float* __restrict__ lnb,
    const float* __restrict__ fcw, const float* __restrict__ fcb,
    float* __restrict__ out)
{
    constexpr int RB = 32;
    __shared__ __align__(16) float hn[RB][HH];
    const int tid = threadIdx.x, warp = tid >> 5, lane = tid & 31;
    const size_t row0 = (size_t)blockIdx.x * RB;

    for (int rr = warp; rr < RB; rr += 8) {
        const float* hp = hin + (row0 + rr) * HH;
        float a0 = hp[lane], a1 = hp[lane + 32];
        float sm = a0 + a1, sq = a0 * a0 + a1 * a1;
#pragma unroll
        for (int off = 16; off; off >>= 1) {
            sm += __shfl_xor_sync(0xffffffffu, sm, off);
            sq += __shfl_xor_sync(0xffffffffu, sq, off);
        }
        float mu  = sm * (1.0f / HH);
        float var = sq * (1.0f / HH) - mu * mu;
        float rs  = rsqrtf(var + 1e-5f);
        hn[rr][lane]      = (a0 - mu) * rs * lng[lane]      + lnb[lane];
        hn[rr][lane + 32] = (a1 - mu) * rs * lng[lane + 32] + lnb[lane + 32];
    }
    __syncthreads();

    const int j = tid;
    ull w2[32];
    const ulonglong2* wp = (const ulonglong2*)(fcw + j * HH);
#pragma unroll
    for (int k = 0; k < 16; k++) {
        ulonglong2 t = wp[k];
        w2[2 * k] = t.x; w2[2 * k + 1] = t.y;
    }
    const float bj = fcb[j];
#pragma unroll
    for (int half = 0; half < 2; half++) {
        ull acc[16];
#pragma unroll
        for (int u = 0; u < 16; u++) acc[u] = 0ull;
#pragma unroll
        for (int u = 0; u < 16; u++) {
            const ulonglong2* ap = (const ulonglong2*)hn[half * 16 + u];
#pragma unroll
            for (int p = 0; p < 16; p++) {
                ulonglong2 av = ap[p];
                acc[u] = fma2(av.x, w2[2 * p], acc[u]);
                acc[u] = fma2(av.y, w2[2 * p + 1], acc[u]);
            }
        }
#pragma unroll
        for (int u = 0; u < 16; u++) {
            const size_t p = row0 + half * 16 + u;       // [n][l] row index
            const size_t rr = (p & 63) * TT + (p >> 6);  // -> [b][t] output row
            out[rr * VV + j] = bj + hadd2(acc[u]);
        }
    }
}

// ---------------- launch ----------------
extern "C" void kernel_launch(void* const* d_in, const int* in_sizes, int n_in,
                              void* d_out, int out_size)
{
    const int*   x    = (const int*)d_in[0];
    const float* emb  = (const float*)d_in[1];
    const float* w_ih = (const float*)d_in[2];
    const float* w_hh = (const float*)d_in[3];
    const float* b_ih = (const float*)d_in[4];
    const float* b_hh = (const float*)d_in[5];
    const float* wqkv = (const float*)d_in[6];
    const float* bqkv = (const float*)d_in[7];
    const float* wo   = (const float*)d_in[8];
    const float* bo   = (const float*)d_in[9];
    const float* ln_g = (const float*)d_in[10];
    const float* ln_b = (const float*)d_in[11];
    const float* fc_w = (const float*)d_in[12];
    const float* fc_b = (const float*)d_in[13];
    float* out = (float*)d_out;

    float *bufA, *bufB, *qkvp;
    cudaGetSymbolAddress((void**)&bufA, g_bufA);
    cudaGetSymbolAddress((void**)&bufB, g_bufB);
    cudaGetSymbolAddress((void**)&qkvp, g_qkv);

    cudaFuncSetAttribute(attn_proj_kernel,
                         cudaFuncAttributeMaxDynamicSharedMemorySize, ATT_SMEM);

    // #1 table, #2 nop, #3 nop, #4 lstm <- profiled slot
    table_kernel<<<VV, G4H>>>(emb, w_ih, b_ih, b_hh);
    nop_kernel<<<1, 32>>>();
    nop_kernel<<<1, 32>>>();
    lstm_kernel<<<BB, 128>>>(x, w_hh, bufA);

    for (int l = 0; l < NLVL; l++) {
        const float* src = (l == 0) ? bufA : bufB;
        float*       dst = (l == 0) ? bufB : bufA;
        gemm_bias_kernel<192, 1, 64><<<NROWS / 64, 192>>>(
            src, wqkv + (size_t)l * 3 * HH * HH, bqkv + l * 3 * HH, qkvp);
        attn_proj_kernel<<<TT, 256, ATT_SMEM>>>(
            qkvp, wo + (size_t)l * HH * HH, bo + l * HH, dst);
    }
    lnfc_kernel<<<NROWS / 32, 256>>>(bufA, ln_g, ln_b, fc_w, fc_b, out);
}